// round 13
// baseline (speedup 1.0000x reference)
#include <cuda_runtime.h>
#include <cuda_bf16.h>

#define DIM 4096
#define TOTAL 16384
#define WIDTH 4
#define STATE_LEN 3
#define NSLOTS 256
#define BATCH 8

#define TPB 256
#define EPT 8                                        // floats per thread per group
#define KG 2                                         // groups per thread
#define GROUP_FLOATS (TPB * EPT)                     // 2048
#define CHUNK (KG * GROUP_FLOATS)                    // 4096 floats per block
#define XBLKS (TOTAL / CHUNK)                        // 4
#define CONV_BLOCKS (DIM * XBLKS)                    // 16384
#define STATE_FLOATS (NSLOTS * DIM * STATE_LEN)      // 3,145,728
#define STATE_BLOCKS (STATE_FLOATS / 4 / TPB)        // 3072

// 256-bit global load (LDG.E.256 on sm_100+).
__device__ __forceinline__ void ldg256(const float* p, float* v) {
    asm volatile(
        "ld.global.v8.f32 {%0,%1,%2,%3,%4,%5,%6,%7}, [%8];"
        : "=f"(v[0]), "=f"(v[1]), "=f"(v[2]), "=f"(v[3]),
          "=f"(v[4]), "=f"(v[5]), "=f"(v[6]), "=f"(v[7])
        : "l"(p));
}

// 256-bit streaming global store (STG.E.256 .cs).
__device__ __forceinline__ void stg256_cs(float* p, const float* v) {
    asm volatile(
        "st.global.cs.v8.f32 [%0], {%1,%2,%3,%4,%5,%6,%7,%8};"
        :: "l"(p),
           "f"(v[0]), "f"(v[1]), "f"(v[2]), "f"(v[3]),
           "f"(v[4]), "f"(v[5]), "f"(v[6]), "f"(v[7])
        : "memory");
}

__global__ void __launch_bounds__(TPB) fused_conv_kernel(
    const float* __restrict__ x,
    const float* __restrict__ weight,
    const float* __restrict__ cs,
    const int* __restrict__ qsl,
    const int* __restrict__ ci,
    const int* __restrict__ im,
    const int* __restrict__ pad,
    const int* __restrict__ resc,
    float* __restrict__ out,
    float* __restrict__ out_states)
{
    __shared__ int   s_qsl[BATCH + 1];
    __shared__ int   s_ci[BATCH];
    __shared__ int   s_im[BATCH];
    __shared__ int   s_pad;
    __shared__ float s_res;
    // Tail exchange: thread t publishes x[base+5..7] so thread t+1 gets its
    // 3 boundary taps from smem instead of a fragmented global load.
    __shared__ float s_m1[KG][TPB];   // x[base+7]
    __shared__ float s_m2[KG][TPB];   // x[base+6]
    __shared__ float s_m3[KG][TPB];   // x[base+5]

    if (threadIdx.x < BATCH + 1) s_qsl[threadIdx.x] = qsl[threadIdx.x];
    if (threadIdx.x < BATCH) {
        s_ci[threadIdx.x] = ci[threadIdx.x];
        s_im[threadIdx.x] = im[threadIdx.x];
    }
    if (threadIdx.x == 0) {
        s_pad = pad[0];
        s_res = resc[0] ? 1.0f : 0.0f;
    }
    __syncthreads();

    const int bid = blockIdx.x;
    const int tid = threadIdx.x;

    if (bid < CONV_BLOCKS) {
        // ----------------- conv region -----------------
        const int d    = bid >> 2;                    // bid / XBLKS
        const int xblk = bid & (XBLKS - 1);
        const int base = xblk * CHUNK + tid * EPT;    // 32B aligned

        const float4 wv = *(const float4*)(weight + (size_t)d * WIDTH);
        const float w0 = wv.x, w1 = wv.y, w2 = wv.z;
        const float w3r = wv.w + s_res;

        const float* xr = x + (size_t)d * TOTAL;

        // Front-batch the 2 LDG.256 (the only DRAM reads for this block).
        float c[KG][EPT];
#pragma unroll
        for (int k = 0; k < KG; k++)
            ldg256(xr + base + k * GROUP_FLOATS, c[k]);

        // Publish tails, exchange through smem.
#pragma unroll
        for (int k = 0; k < KG; k++) {
            s_m1[k][tid] = c[k][7];
            s_m2[k][tid] = c[k][6];
            s_m3[k][tid] = c[k][5];
        }
        __syncthreads();

        float pm1[KG], pm2[KG], pm3[KG];
        if (tid > 0) {
#pragma unroll
            for (int k = 0; k < KG; k++) {
                pm1[k] = s_m1[k][tid - 1];
                pm2[k] = s_m2[k][tid - 1];
                pm3[k] = s_m3[k][tid - 1];
            }
        } else {
            // Block-leading thread: previous chunk lives outside this block.
#pragma unroll
            for (int k = 0; k < KG; k++) {
                const int t0 = base + k * GROUP_FLOATS;
                const float4 pv =
                    *(const float4*)(xr + (t0 >= 4 ? t0 - 4 : 0));
                pm1[k] = pv.w; pm2[k] = pv.z; pm3[k] = pv.y;
            }
        }

        const float wk[3] = {w2, w1, w0};
#pragma unroll
        for (int k = 0; k < KG; k++) {
            const int t0 = base + k * GROUP_FLOATS;
            int seg = 0;
#pragma unroll
            for (int i = 1; i < BATCH; i++) seg += (t0 >= s_qsl[i]);

            float o[EPT];
            if (t0 - s_qsl[seg] >= STATE_LEN && t0 + EPT - 1 < s_qsl[seg + 1]) {
                o[0] = c[k][0] * w3r + w2 * pm1[k]  + w1 * pm2[k]  + w0 * pm3[k];
                o[1] = c[k][1] * w3r + w2 * c[k][0] + w1 * pm1[k]  + w0 * pm2[k];
                o[2] = c[k][2] * w3r + w2 * c[k][1] + w1 * c[k][0] + w0 * pm1[k];
#pragma unroll
                for (int e = 3; e < EPT; e++)
                    o[e] = c[k][e] * w3r + w2 * c[k][e-1] + w1 * c[k][e-2]
                         + w0 * c[k][e-3];
            } else {
#pragma unroll
                for (int e = 0; e < EPT; e++) {
                    const int t = t0 + e;
                    int sg = 0;
#pragma unroll
                    for (int i = 1; i < BATCH; i++) sg += (t >= s_qsl[i]);
                    const int  p        = t - s_qsl[sg];
                    const int  raw      = s_ci[sg];
                    const bool valid    = (raw != s_pad);
                    const int  slot     = valid ? raw : 0;
                    const bool use_init = valid && (s_im[sg] != 0);

                    float acc = xr[t] * w3r;
#pragma unroll
                    for (int joff = 1; joff < WIDTH; joff++) {
                        float v;
                        if (p >= joff) {
                            v = xr[t - joff];
                        } else if (use_init) {
                            v = cs[((size_t)slot * DIM + d) * STATE_LEN +
                                   (STATE_LEN - joff + p)];
                        } else {
                            v = 0.0f;
                        }
                        acc += wk[joff - 1] * v;
                    }
                    o[e] = acc;
                }
            }
            stg256_cs(out + (size_t)d * TOTAL + t0, o);
        }
    } else {
        // ----------------- state region -----------------
        const int sb   = bid - CONV_BLOCKS;
        const int f0   = (sb * TPB + tid) * 4;
        const int slot = f0 / (DIM * STATE_LEN);

        int wb = -1;
#pragma unroll
        for (int b = 0; b < BATCH; b++) {
            if (s_ci[b] == slot && s_ci[b] != s_pad) wb = b;
        }

        if (wb < 0) {
            const float4 v = __ldcs((const float4*)(cs + f0));
            __stcs((float4*)(out_states + f0), v);
        } else {
            const int start = s_qsl[wb];
            const int end   = s_qsl[wb + 1];
            const int L     = end - start;
            const bool init = (s_im[wb] != 0);
            float r[4];
#pragma unroll
            for (int cc = 0; cc < 4; cc++) {
                const int f  = f0 + cc;
                const int rm = f - slot * (DIM * STATE_LEN);
                const int dd = rm / STATE_LEN;
                const int j  = rm - dd * STATE_LEN;
                const int gx = end + j - STATE_LEN;
                float v;
                if (gx >= start) {
                    v = x[(size_t)dd * TOTAL + gx];
                } else if (init) {
                    int sidx = L + j;
                    sidx = sidx < 0 ? 0 :
                           (sidx > STATE_LEN - 1 ? STATE_LEN - 1 : sidx);
                    v = cs[((size_t)slot * DIM + dd) * STATE_LEN + sidx];
                } else {
                    v = 0.0f;
                }
                r[cc] = v;
            }
            __stcs((float4*)(out_states + f0),
                   make_float4(r[0], r[1], r[2], r[3]));
        }
    }
}

extern "C" void kernel_launch(void* const* d_in, const int* in_sizes, int n_in,
                              void* d_out, int out_size) {
    const float* x    = (const float*)d_in[0];
    const float* w    = (const float*)d_in[1];
    const float* cs   = (const float*)d_in[2];
    const int*   qsl  = (const int*)d_in[3];
    const int*   ci   = (const int*)d_in[4];
    const int*   im   = (const int*)d_in[5];
    const int*   pad  = (const int*)d_in[6];
    const int*   resc = (const int*)d_in[7];

    float* out        = (float*)d_out;
    float* out_states = out + (size_t)DIM * TOTAL;

    fused_conv_kernel<<<CONV_BLOCKS + STATE_BLOCKS, TPB>>>(
        x, w, cs, qsl, ci, im, pad, resc, out, out_states);
}

// round 14
// speedup vs baseline: 1.0501x; 1.0501x over previous
#include <cuda_runtime.h>
#include <cuda_bf16.h>

#define DIM 4096
#define TOTAL 16384
#define WIDTH 4
#define STATE_LEN 3
#define NSLOTS 256
#define BATCH 8

#define TPB 256
#define EPT 8                                        // floats per thread per group
#define KG 2                                         // groups per thread
#define GROUP_FLOATS (TPB * EPT)                     // 2048
#define CHUNK (KG * GROUP_FLOATS)                    // 4096 floats per block
#define XBLKS (TOTAL / CHUNK)                        // 4
#define CONV_BLOCKS (DIM * XBLKS)                    // 16384
#define STATE_FLOATS (NSLOTS * DIM * STATE_LEN)      // 3,145,728
#define STATE_BLOCKS (STATE_FLOATS / 4 / TPB)        // 3072

// 256-bit global load (LDG.E.256 on sm_100+).
__device__ __forceinline__ void ldg256(const float* p, float* v) {
    asm volatile(
        "ld.global.v8.f32 {%0,%1,%2,%3,%4,%5,%6,%7}, [%8];"
        : "=f"(v[0]), "=f"(v[1]), "=f"(v[2]), "=f"(v[3]),
          "=f"(v[4]), "=f"(v[5]), "=f"(v[6]), "=f"(v[7])
        : "l"(p));
}

// 256-bit streaming global store (STG.E.256 .cs).
__device__ __forceinline__ void stg256_cs(float* p, const float* v) {
    asm volatile(
        "st.global.cs.v8.f32 [%0], {%1,%2,%3,%4,%5,%6,%7,%8};"
        :: "l"(p),
           "f"(v[0]), "f"(v[1]), "f"(v[2]), "f"(v[3]),
           "f"(v[4]), "f"(v[5]), "f"(v[6]), "f"(v[7])
        : "memory");
}

__global__ void __launch_bounds__(TPB, 6) fused_conv_kernel(
    const float* __restrict__ x,
    const float* __restrict__ weight,
    const float* __restrict__ cs,
    const int* __restrict__ qsl,
    const int* __restrict__ ci,
    const int* __restrict__ im,
    const int* __restrict__ pad,
    const int* __restrict__ resc,
    float* __restrict__ out,
    float* __restrict__ out_states)
{
    __shared__ int   s_qsl[BATCH + 1];
    __shared__ int   s_ci[BATCH];
    __shared__ int   s_im[BATCH];
    __shared__ int   s_pad;
    __shared__ float s_res;
    // Tail exchange: thread t publishes x[base+5..7] so thread t+1 gets its
    // 3 boundary taps from smem instead of a fragmented global load.
    __shared__ float s_m1[KG][TPB];   // x[base+7]
    __shared__ float s_m2[KG][TPB];   // x[base+6]
    __shared__ float s_m3[KG][TPB];   // x[base+5]

    if (threadIdx.x < BATCH + 1) s_qsl[threadIdx.x] = qsl[threadIdx.x];
    if (threadIdx.x < BATCH) {
        s_ci[threadIdx.x] = ci[threadIdx.x];
        s_im[threadIdx.x] = im[threadIdx.x];
    }
    if (threadIdx.x == 0) {
        s_pad = pad[0];
        s_res = resc[0] ? 1.0f : 0.0f;
    }
    __syncthreads();

    const int bid = blockIdx.x;
    const int tid = threadIdx.x;

    if (bid < CONV_BLOCKS) {
        // ----------------- conv region -----------------
        const int d    = bid >> 2;                    // bid / XBLKS
        const int xblk = bid & (XBLKS - 1);
        const int base = xblk * CHUNK + tid * EPT;    // 32B aligned

        const float4 wv = *(const float4*)(weight + (size_t)d * WIDTH);
        const float w0 = wv.x, w1 = wv.y, w2 = wv.z;
        const float w3r = wv.w + s_res;

        const float* xr = x + (size_t)d * TOTAL;

        // Front-batch the 2 LDG.256 (the only DRAM reads for this block).
        float c[KG][EPT];
#pragma unroll
        for (int k = 0; k < KG; k++)
            ldg256(xr + base + k * GROUP_FLOATS, c[k]);

        // Publish tails, exchange through smem.
#pragma unroll
        for (int k = 0; k < KG; k++) {
            s_m1[k][tid] = c[k][7];
            s_m2[k][tid] = c[k][6];
            s_m3[k][tid] = c[k][5];
        }
        __syncthreads();

        float pm1[KG], pm2[KG], pm3[KG];
        if (tid > 0) {
#pragma unroll
            for (int k = 0; k < KG; k++) {
                pm1[k] = s_m1[k][tid - 1];
                pm2[k] = s_m2[k][tid - 1];
                pm3[k] = s_m3[k][tid - 1];
            }
        } else {
            // Block-leading thread: previous chunk lives outside this block.
#pragma unroll
            for (int k = 0; k < KG; k++) {
                const int t0 = base + k * GROUP_FLOATS;
                const float4 pv =
                    *(const float4*)(xr + (t0 >= 4 ? t0 - 4 : 0));
                pm1[k] = pv.w; pm2[k] = pv.z; pm3[k] = pv.y;
            }
        }

        const float wk[3] = {w2, w1, w0};
#pragma unroll
        for (int k = 0; k < KG; k++) {
            const int t0 = base + k * GROUP_FLOATS;
            int seg = 0;
#pragma unroll
            for (int i = 1; i < BATCH; i++) seg += (t0 >= s_qsl[i]);

            float o[EPT];
            if (t0 - s_qsl[seg] >= STATE_LEN && t0 + EPT - 1 < s_qsl[seg + 1]) {
                o[0] = c[k][0] * w3r + w2 * pm1[k]  + w1 * pm2[k]  + w0 * pm3[k];
                o[1] = c[k][1] * w3r + w2 * c[k][0] + w1 * pm1[k]  + w0 * pm2[k];
                o[2] = c[k][2] * w3r + w2 * c[k][1] + w1 * c[k][0] + w0 * pm1[k];
#pragma unroll
                for (int e = 3; e < EPT; e++)
                    o[e] = c[k][e] * w3r + w2 * c[k][e-1] + w1 * c[k][e-2]
                         + w0 * c[k][e-3];
            } else {
#pragma unroll
                for (int e = 0; e < EPT; e++) {
                    const int t = t0 + e;
                    int sg = 0;
#pragma unroll
                    for (int i = 1; i < BATCH; i++) sg += (t >= s_qsl[i]);
                    const int  p        = t - s_qsl[sg];
                    const int  raw      = s_ci[sg];
                    const bool valid    = (raw != s_pad);
                    const int  slot     = valid ? raw : 0;
                    const bool use_init = valid && (s_im[sg] != 0);

                    float acc = xr[t] * w3r;
#pragma unroll
                    for (int joff = 1; joff < WIDTH; joff++) {
                        float v;
                        if (p >= joff) {
                            v = xr[t - joff];
                        } else if (use_init) {
                            v = cs[((size_t)slot * DIM + d) * STATE_LEN +
                                   (STATE_LEN - joff + p)];
                        } else {
                            v = 0.0f;
                        }
                        acc += wk[joff - 1] * v;
                    }
                    o[e] = acc;
                }
            }
            stg256_cs(out + (size_t)d * TOTAL + t0, o);
        }
    } else {
        // ----------------- state region -----------------
        const int sb   = bid - CONV_BLOCKS;
        const int f0   = (sb * TPB + tid) * 4;
        const int slot = f0 / (DIM * STATE_LEN);

        int wb = -1;
#pragma unroll
        for (int b = 0; b < BATCH; b++) {
            if (s_ci[b] == slot && s_ci[b] != s_pad) wb = b;
        }

        if (wb < 0) {
            const float4 v = __ldcs((const float4*)(cs + f0));
            __stcs((float4*)(out_states + f0), v);
        } else {
            const int start = s_qsl[wb];
            const int end   = s_qsl[wb + 1];
            const int L     = end - start;
            const bool init = (s_im[wb] != 0);
            float r[4];
#pragma unroll
            for (int cc = 0; cc < 4; cc++) {
                const int f  = f0 + cc;
                const int rm = f - slot * (DIM * STATE_LEN);
                const int dd = rm / STATE_LEN;
                const int j  = rm - dd * STATE_LEN;
                const int gx = end + j - STATE_LEN;
                float v;
                if (gx >= start) {
                    v = x[(size_t)dd * TOTAL + gx];
                } else if (init) {
                    int sidx = L + j;
                    sidx = sidx < 0 ? 0 :
                           (sidx > STATE_LEN - 1 ? STATE_LEN - 1 : sidx);
                    v = cs[((size_t)slot * DIM + dd) * STATE_LEN + sidx];
                } else {
                    v = 0.0f;
                }
                r[cc] = v;
            }
            __stcs((float4*)(out_states + f0),
                   make_float4(r[0], r[1], r[2], r[3]));
        }
    }
}

extern "C" void kernel_launch(void* const* d_in, const int* in_sizes, int n_in,
                              void* d_out, int out_size) {
    const float* x    = (const float*)d_in[0];
    const float* w    = (const float*)d_in[1];
    const float* cs   = (const float*)d_in[2];
    const int*   qsl  = (const int*)d_in[3];
    const int*   ci   = (const int*)d_in[4];
    const int*   im   = (const int*)d_in[5];
    const int*   pad  = (const int*)d_in[6];
    const int*   resc = (const int*)d_in[7];

    float* out        = (float*)d_out;
    float* out_states = out + (size_t)DIM * TOTAL;

    fused_conv_kernel<<<CONV_BLOCKS + STATE_BLOCKS, TPB>>>(
        x, w, cs, qsl, ci, im, pad, resc, out, out_states);
}